// round 1
// baseline (speedup 1.0000x reference)
#include <cuda_runtime.h>
#include <cstdint>

// Problem constants
#define BB     8
#define RR     2048
#define CC     4096
#define NROWS  (BB * RR)            // 16384 score rows
#define WORDS  (CC / 32)            // 128 mask words per row
#define K_FRONT 1228                // int(4096*0.30)
#define K_RAND  409                 // int(4096*0.10)

// PRNG mode: 1 = jax_threefry_partitionable (default in modern JAX):
//   bits(i) = t0 ^ t1 where (t0,t1) = threefry2x32(key, (hi32(i)=0, lo32(i)=i))
// 0 = legacy split-counter mode:
//   counts = iota(2^26), split halves; bits(i<2^25)=out0 of (i, i+2^25); else out1.
#define PRNG_PARTITIONABLE 1

// ---- scratch (device globals; no allocation allowed) ----
__device__ uint32_t g_smask[NROWS * WORDS];   // student keep-bits, 8 MB
__device__ uint32_t g_front0[BB * WORDS];     // front-sel bits for row 0 of each batch

// ---- threefry2x32, key = (0, 42) baked in ----
// ks = [0, 42, 0x1BD11BDA ^ 0 ^ 42 = 0x1BD11BF0]
__device__ __forceinline__ void threefry_0_42(uint32_t c0, uint32_t c1,
                                              uint32_t& o0, uint32_t& o1) {
    uint32_t x0 = c0 + 0u;
    uint32_t x1 = c1 + 42u;
#define TF_RND(r) { x0 += x1; x1 = __funnelshift_l(x1, x1, (r)); x1 ^= x0; }
    TF_RND(13) TF_RND(15) TF_RND(26) TF_RND(6)
    x0 += 42u;          x1 += 0x1BD11BF1u;   // ks1, ks2+1
    TF_RND(17) TF_RND(29) TF_RND(16) TF_RND(24)
    x0 += 0x1BD11BF0u;  x1 += 2u;            // ks2, ks0+2
    TF_RND(13) TF_RND(15) TF_RND(26) TF_RND(6)
    x0 += 0u;           x1 += 45u;           // ks0, ks1+3
    TF_RND(17) TF_RND(29) TF_RND(16) TF_RND(24)
    x0 += 42u;          x1 += 0x1BD11BF4u;   // ks1, ks2+4
    TF_RND(13) TF_RND(15) TF_RND(26) TF_RND(6)
    x0 += 0x1BD11BF0u;  x1 += 5u;            // ks2, ks0+5
#undef TF_RND
    o0 = x0; o1 = x1;
}

// 23-bit ordering key of jax.random.uniform at flat index g (g < 2^26)
__device__ __forceinline__ uint32_t rand_key(uint32_t g) {
    uint32_t o0, o1;
#if PRNG_PARTITIONABLE
    threefry_0_42(0u, g, o0, o1);
    uint32_t bits = o0 ^ o1;
#else
    uint32_t bits;
    if (g < (1u << 25)) { threefry_0_42(g, g + (1u << 25), o0, o1); bits = o0; }
    else { uint32_t p = g - (1u << 25); threefry_0_42(p, p + (1u << 25), o0, o1); bits = o1; }
#endif
    return bits >> 9;   // uniform value ordering == ordering of these 23 bits
}

__device__ __forceinline__ uint32_t warp_exscan(uint32_t v, int lane) {
    uint32_t x = v;
#pragma unroll
    for (int d = 1; d < 32; d <<= 1) {
        uint32_t y = __shfl_up_sync(0xFFFFFFFFu, x, d);
        if (lane >= d) x += y;
    }
    return x - v;
}

// ============================================================================
// Kernel 1: one block per score row. Computes front & rand thresholds via
// radix select (stable, index-tie-broken) and writes packed keep-masks.
// ============================================================================
#define T1  512
#define EPT 8   // 512*8 = 4096 elems

__global__ __launch_bounds__(T1) void k1_select(const float* __restrict__ score) {
    const int q = blockIdx.x;              // row id in [0, 16384)
    const int t = threadIdx.x;
    const int wi = t >> 5, lane = t & 31;
    const uint32_t lmask_lt = (1u << lane) - 1u;

    const float* row = score + (size_t)q * CC;

    uint32_t skey[EPT], rkey[EPT];
#pragma unroll
    for (int j = 0; j < EPT; j++) {
        int c = j * T1 + t;
        uint32_t u = __float_as_uint(row[c]);
        skey[j] = u ^ ((u & 0x80000000u) ? 0xFFFFFFFFu : 0x80000000u); // ascending-order uint
        rkey[j] = rand_key((uint32_t)(q * CC + c));
    }

    __shared__ uint32_t hist[256];
    __shared__ uint32_t s_ctl[2];          // {new_prefix, new_kk}
    __shared__ uint32_t s_pre[WORDS];      // per-word prefix (reused per select)

    uint32_t Tsel[2]; uint32_t need[2];

    for (int sel = 0; sel < 2; sel++) {
        const uint32_t K = sel ? (uint32_t)K_RAND : (uint32_t)K_FRONT;
        const int npass = sel ? 3 : 4;     // rand keys are 23-bit
        uint32_t prefix = 0, kk = K - 1;   // rank of the threshold element

        for (int pass = 0; pass < npass; pass++) {
            const int shift = 8 * (npass - 1 - pass);
            if (t < 256) hist[t] = 0;
            __syncthreads();
#pragma unroll
            for (int j = 0; j < EPT; j++) {
                uint32_t key = sel ? rkey[j] : skey[j];
                bool match;
                if (pass == 0) match = true;
                else           match = ((key >> (shift + 8)) == prefix);
                if (match) atomicAdd(&hist[(key >> shift) & 255u], 1u);
            }
            __syncthreads();
            if (t < 32) {
                uint32_t h[8]; uint32_t sum = 0;
#pragma unroll
                for (int b2 = 0; b2 < 8; b2++) { h[b2] = hist[8 * t + b2]; sum += h[b2]; }
                uint32_t run = warp_exscan(sum, t);
#pragma unroll
                for (int b2 = 0; b2 < 8; b2++) {
                    if (kk >= run && kk < run + h[b2]) {
                        s_ctl[0] = (prefix << 8) | (uint32_t)(8 * t + b2);
                        s_ctl[1] = kk - run;
                    }
                    run += h[b2];
                }
            }
            __syncthreads();
            prefix = s_ctl[0];
            kk = s_ctl[1];
            __syncthreads();
        }
        Tsel[sel] = prefix;        // value at rank K-1
        need[sel] = kk + 1;        // # of ==T elements to take (lowest index first)
    }

    const uint32_t Tf = Tsel[0], Tr = Tsel[1];

    // ---- exact tie-break: per-word counts of ==T, then exclusive prefix ----
    __shared__ uint32_t s_pref_f[WORDS];
#pragma unroll
    for (int j = 0; j < EPT; j++) {
        uint32_t bf = __ballot_sync(0xFFFFFFFFu, skey[j] == Tf);
        uint32_t br = __ballot_sync(0xFFFFFFFFu, rkey[j] == Tr);
        if (lane == 0) {
            s_pref_f[j * 16 + wi] = __popc(bf);
            s_pre[j * 16 + wi]    = __popc(br);
        }
    }
    __syncthreads();
    if (t < 32) {  // exclusive prefix over 128 words, both arrays (4 words/lane)
        uint32_t a[4], b[4], sa = 0, sb = 0;
#pragma unroll
        for (int i = 0; i < 4; i++) { a[i] = s_pref_f[4 * t + i]; sa += a[i];
                                      b[i] = s_pre[4 * t + i];    sb += b[i]; }
        uint32_t ea = warp_exscan(sa, t), eb = warp_exscan(sb, t);
#pragma unroll
        for (int i = 0; i < 4; i++) {
            s_pref_f[4 * t + i] = ea; ea += a[i];
            s_pre[4 * t + i]    = eb; eb += b[i];
        }
    }
    __syncthreads();

    // ---- final mask computation + packed writes ----
    const bool is_row0 = ((q & (RR - 1)) == 0);
#pragma unroll
    for (int j = 0; j < EPT; j++) {
        const int w = j * 16 + wi;
        uint32_t bf = __ballot_sync(0xFFFFFFFFu, skey[j] == Tf);
        uint32_t br = __ballot_sync(0xFFFFFFFFu, rkey[j] == Tr);
        bool fsel = (skey[j] < Tf) ||
                    ((skey[j] == Tf) && (s_pref_f[w] + __popc(bf & lmask_lt) < need[0]));
        bool rsel = (rkey[j] < Tr) ||
                    ((rkey[j] == Tr) && (s_pre[w] + __popc(br & lmask_lt) < need[1]));
        uint32_t keep_w  = __ballot_sync(0xFFFFFFFFu, !(fsel || rsel));
        uint32_t front_w = __ballot_sync(0xFFFFFFFFu, fsel);
        if (lane == 0) {
            g_smask[q * WORDS + w] = keep_w;
            if (is_row0) g_front0[(q >> 11) * WORDS + w] = front_w;
        }
    }
}

// ============================================================================
// Kernel 2: per-batch [4096 x 2048] transpose with mask application.
// out_student[b][j][m] = mask * score[b].flat[m*2048+j]; same for teacher.
// ============================================================================
__global__ __launch_bounds__(256) void k2_transpose(const float* __restrict__ score,
                                                    float* __restrict__ out_s,
                                                    float* __restrict__ out_t) {
    __shared__ float ss[32][33];
    __shared__ float st[32][33];
    const int b  = blockIdx.z;
    const int m0 = blockIdx.y * 32;
    const int j0 = blockIdx.x * 32;
    const int tx = threadIdx.x, ty = threadIdx.y;   // (32, 8)

    const float* base = score + (size_t)b * (RR * CC);
#pragma unroll
    for (int k = 0; k < 4; k++) {
        int m = m0 + ty + 8 * k;
        int j = j0 + tx;
        float v = base[(size_t)m * 2048 + j];
        int r = m >> 1;
        int c = ((m & 1) << 11) + j;
        int q = b * RR + r;
        uint32_t mw = g_smask[q * WORDS + (c >> 5)];
        float vs = ((mw >> (c & 31)) & 1u) ? v : 0.0f;
        float vt;
        if (r == 0) {
            uint32_t fw = g_front0[b * WORDS + (c >> 5)];
            vt = ((fw >> (c & 31)) & 1u) ? v : 0.0f;
        } else {
            vt = v;     // reference teacher-mask bug: rows 1.. stay all-ones
        }
        ss[ty + 8 * k][tx] = vs;
        st[ty + 8 * k][tx] = vt;
    }
    __syncthreads();

    float* os = out_s + (size_t)b * (RR * CC);
    float* ot = out_t + (size_t)b * (RR * CC);
#pragma unroll
    for (int k = 0; k < 4; k++) {
        int j = j0 + ty + 8 * k;
        int m = m0 + tx;
        os[(size_t)j * CC + m] = ss[tx][ty + 8 * k];
        ot[(size_t)j * CC + m] = st[tx][ty + 8 * k];
    }
}

// ============================================================================
extern "C" void kernel_launch(void* const* d_in, const int* in_sizes, int n_in,
                              void* d_out, int out_size) {
    const float* score = (const float*)d_in[0];
    float* out = (float*)d_out;
    float* out_teacher = out + (size_t)BB * RR * CC;   // student first, teacher second

    k1_select<<<NROWS, T1>>>(score);

    dim3 grid(CC / 2 / 32, CC / 32, BB);   // (j-tiles=64, m-tiles=128, batch=8)
    dim3 blk(32, 8);
    k2_transpose<<<grid, blk>>>(score, out, out_teacher);
}